// round 1
// baseline (speedup 1.0000x reference)
#include <cuda_runtime.h>
#include <cstdint>

#define FDIM 1024           // features
#define FV   256            // float4 per row
#define DDOM 8              // domains
#define RPB  64             // rows per block, pass1
#define RPB2 16             // rows per block, pass2
#define NBMAX 256           // pass1 blocks (16384 / 64)
#define EPSV 1e-5f

// Scratch (allocation-free: __device__ globals)
__device__ float g_P1[NBMAX * DDOM * FDIM];   // per-block partial sum(x)
__device__ float g_P2[NBMAX * DDOM * FDIM];   // per-block partial sum(x*x)
__device__ int   g_cntp[NBMAX * DDOM];        // per-block domain counts
__device__ float g_A[DDOM * FDIM];            // gamma*inv
__device__ float g_B[DDOM * FDIM];            // beta - mean*gamma*inv

// Detect whether y is int64 (little-endian: high words at odd int slots are 0)
// or int32. 16 odd slots checked; false positive prob for random 0..7 int32
// data = 8^-16 ~ 3.5e-15.
__device__ __forceinline__ int detect64(const int* __restrict__ y) {
    const int4* p = (const int4*)y;
    int acc = 0;
#pragma unroll
    for (int i = 0; i < 8; i++) {
        int4 a = p[i];
        acc |= a.y | a.w;
    }
    return acc == 0;
}

// Warp-uniform domain accumulate (all threads in a block share the row's domain)
#define ACC1(d, v)                                                   \
    s1[d].x += v.x; s1[d].y += v.y; s1[d].z += v.z; s1[d].w += v.w;  \
    s2[d].x = fmaf(v.x, v.x, s2[d].x);                               \
    s2[d].y = fmaf(v.y, v.y, s2[d].y);                               \
    s2[d].z = fmaf(v.z, v.z, s2[d].z);                               \
    s2[d].w = fmaf(v.w, v.w, s2[d].w);                               \
    cnt[d] += cone;

#define ACC(dd, v) do { switch (dd) {                                \
    case 0: ACC1(0, v); break; case 1: ACC1(1, v); break;            \
    case 2: ACC1(2, v); break; case 3: ACC1(3, v); break;            \
    case 4: ACC1(4, v); break; case 5: ACC1(5, v); break;            \
    case 6: ACC1(6, v); break; default: ACC1(7, v); break; } } while (0)

__global__ __launch_bounds__(256, 2)
void pass1_k(const float4* __restrict__ x4, const int* __restrict__ yi, int n) {
    const int b = blockIdx.x;
    const int tid = threadIdx.x;
    const int is64 = detect64(yi);
    const int cone = (tid == 0) ? 1 : 0;

    float4 s1[DDOM], s2[DDOM];
    int cnt[DDOM];
#pragma unroll
    for (int d = 0; d < DDOM; d++) {
        s1[d] = make_float4(0.f, 0.f, 0.f, 0.f);
        s2[d] = make_float4(0.f, 0.f, 0.f, 0.f);
        cnt[d] = 0;
    }

    const int r0 = b * RPB;
    const int rend = min(r0 + RPB, n);
    const int step = is64 ? 2 : 1;

    for (int r = r0; r + 3 < rend; r += 4) {
        const int i0 = is64 ? 2 * r : r;
        const int d0 = yi[i0];
        const int d1 = yi[i0 + step];
        const int d2 = yi[i0 + 2 * step];
        const int d3 = yi[i0 + 3 * step];
        const float4* p = x4 + (size_t)r * FV + tid;
        float4 v0 = __ldcg(p);
        float4 v1 = __ldcg(p + FV);
        float4 v2 = __ldcg(p + 2 * FV);
        float4 v3 = __ldcg(p + 3 * FV);
        ACC(d0, v0);
        ACC(d1, v1);
        ACC(d2, v2);
        ACC(d3, v3);
    }

#pragma unroll
    for (int d = 0; d < DDOM; d++) {
        size_t o = ((size_t)b * DDOM + d) * FDIM + tid * 4;
        *(float4*)&g_P1[o] = s1[d];
        *(float4*)&g_P2[o] = s2[d];
    }
    if (tid == 0) {
#pragma unroll
        for (int d = 0; d < DDOM; d++) g_cntp[b * DDOM + d] = cnt[d];
    }
}

__global__ __launch_bounds__(256)
void reduce_k(const float* __restrict__ gamma, const float* __restrict__ beta, int nb) {
    const int o = blockIdx.x * blockDim.x + threadIdx.x;   // 0..8191
    const int d = o >> 10;
    const int f = o & 1023;

    float a1 = 0.f, a1b = 0.f, a2 = 0.f, a2b = 0.f;
#pragma unroll 8
    for (int b = 0; b < nb; b += 2) {
        size_t i0 = ((size_t)b * DDOM + d) * FDIM + f;
        size_t i1 = i0 + (size_t)DDOM * FDIM;
        a1  += g_P1[i0];
        a1b += g_P1[i1];
        a2  += g_P2[i0];
        a2b += g_P2[i1];
    }
    a1 += a1b;
    a2 += a2b;

    float c = 0.f;
#pragma unroll 8
    for (int b = 0; b < nb; b++) c += (float)g_cntp[b * DDOM + d];

    float A, Bv;
    if (c > 1.5f) {
        float mean = a1 / c;
        float var  = a2 / c - mean * mean;
        float inv  = rsqrtf(var + EPSV);
        A  = gamma[o] * inv;
        Bv = fmaf(-mean, A, beta[o]);
    } else if (c > 0.5f) {     // single-sample domain: out = x
        A = 1.f; Bv = 0.f;
    } else {                   // empty domain: out = 0 (no rows hit it anyway)
        A = 0.f; Bv = 0.f;
    }
    g_A[o] = A;
    g_B[o] = Bv;
}

__global__ __launch_bounds__(256)
void pass2_k(const float4* __restrict__ x4, const int* __restrict__ yi,
             float4* __restrict__ o4, int n) {
    const int tid = threadIdx.x;
    const int is64 = detect64(yi);
    const float4* A4 = (const float4*)g_A;
    const float4* B4 = (const float4*)g_B;

    const int r0 = blockIdx.x * RPB2;
    const int rend = min(r0 + RPB2, n);

    for (int r = r0; r + 1 < rend; r += 2) {
        const int d0 = is64 ? yi[2 * r] : yi[r];
        const int d1 = is64 ? yi[2 * (r + 1)] : yi[r + 1];
        const float4* p = x4 + (size_t)r * FV + tid;
        float4 v0 = __ldcg(p);
        float4 v1 = __ldcg(p + FV);
        float4 a0 = __ldg(&A4[d0 * FV + tid]);
        float4 b0 = __ldg(&B4[d0 * FV + tid]);
        float4 a1 = __ldg(&A4[d1 * FV + tid]);
        float4 b1 = __ldg(&B4[d1 * FV + tid]);
        float4 w0, w1;
        w0.x = fmaf(v0.x, a0.x, b0.x);
        w0.y = fmaf(v0.y, a0.y, b0.y);
        w0.z = fmaf(v0.z, a0.z, b0.z);
        w0.w = fmaf(v0.w, a0.w, b0.w);
        w1.x = fmaf(v1.x, a1.x, b1.x);
        w1.y = fmaf(v1.y, a1.y, b1.y);
        w1.z = fmaf(v1.z, a1.z, b1.z);
        w1.w = fmaf(v1.w, a1.w, b1.w);
        o4[(size_t)r * FV + tid] = w0;
        o4[(size_t)(r + 1) * FV + tid] = w1;
    }
}

extern "C" void kernel_launch(void* const* d_in, const int* in_sizes, int n_in,
                              void* d_out, int out_size) {
    const float* x     = (const float*)d_in[0];
    const int*   y     = (const int*)d_in[1];
    const float* gamma = (const float*)d_in[2];
    const float* beta  = (const float*)d_in[3];
    float* out = (float*)d_out;

    const int n = in_sizes[1];            // rows (16384)
    const int nb = (n + RPB - 1) / RPB;   // 256 pass1 blocks

    pass1_k<<<nb, 256>>>((const float4*)x, y, n);
    reduce_k<<<(DDOM * FDIM) / 256, 256>>>(gamma, beta, nb);
    pass2_k<<<(n + RPB2 - 1) / RPB2, 256>>>((const float4*)x, y, (float4*)out, n);
}